// round 14
// baseline (speedup 1.0000x reference)
#include <cuda_runtime.h>
#include <cuda_fp16.h>
#include <math.h>
#include <stdint.h>

// -------------------- problem constants --------------------
#define M_N     8192
#define IN_DIM  3000
#define K_PAD   3008        // 47 * 64
#define HID     512
#define LAT     30
#define MAXD    192

#define BM      128
#define BN      256
#define BK      64
#define NCHUNK  (K_PAD / BK)   // 47
#define NSTAGE  4

// SMEM stage layout (bytes): Ah[128x64]=16K, Bh[256x64]=32K
#define A_BYTES   16384
#define B_BYTES   32768
#define STAGE     (A_BYTES + B_BYTES)            // 49152
#define SMEM_TOTAL (NSTAGE * STAGE)              // 196608

// -------------------- static device scratch --------------------
__device__ __align__(16) __half g_Ah[(size_t)M_N * K_PAD];    // 49 MB fp16 A
__device__ __align__(16) __half g_Xh[(size_t)M_N * HID];      // 8 MB fp16 X
__device__ float g_f0[M_N];
__device__ float g_f1[M_N];
__device__ int   g_idx[M_N * MAXD];
__device__ int   g_cnt[M_N];
__device__ __align__(16) __half g_Bhi[(size_t)HID * K_PAD];   // [n][k] fp16
__device__ __align__(16) float  g_W1t[LAT * HID];             // W1 transposed

// -------------------- PTX helpers --------------------
__device__ __forceinline__ uint32_t smem_u32(const void* p) {
    uint32_t a;
    asm("{ .reg .u64 t; cvta.to.shared.u64 t, %1; cvt.u32.u64 %0, t; }"
        : "=r"(a) : "l"(p));
    return a;
}

__device__ __forceinline__ uint32_t sw128(uint32_t off) {
    return off ^ ((off >> 3) & 0x70);
}

__device__ __forceinline__ void cp_async16(uint32_t dst, const void* src) {
    asm volatile("cp.async.cg.shared.global [%0], [%1], 16;"
                 :: "r"(dst), "l"(src));
}
__device__ __forceinline__ void cp_commit() {
    asm volatile("cp.async.commit_group;" ::: "memory");
}

__device__ __forceinline__ void ldmx4(uint32_t* r, uint32_t addr) {
    asm volatile("ldmatrix.sync.aligned.m8n8.x4.shared.b16 {%0,%1,%2,%3}, [%4];"
                 : "=r"(r[0]), "=r"(r[1]), "=r"(r[2]), "=r"(r[3]) : "r"(addr));
}

__device__ __forceinline__ void mma_fp16(float* d, const uint32_t* a,
                                         const uint32_t* b) {
    asm volatile(
        "mma.sync.aligned.m16n8k16.row.col.f32.f16.f16.f32 "
        "{%0,%1,%2,%3}, {%4,%5,%6,%7}, {%8,%9}, {%0,%1,%2,%3};"
        : "+f"(d[0]), "+f"(d[1]), "+f"(d[2]), "+f"(d[3])
        : "r"(a[0]), "r"(a[1]), "r"(a[2]), "r"(a[3]), "r"(b[0]), "r"(b[1]));
}

// -------------------- Kernel 0a: A fp32 -> fp16 (padded K) ------------------
__global__ __launch_bounds__(256)
void convA_kernel(const float* __restrict__ A, __half* __restrict__ Ah)
{
    const int row = blockIdx.y;
    const int q   = blockIdx.x * 256 + threadIdx.x;
    if (q >= K_PAD / 4) return;
    __half2 h0, h1;
    if (q < IN_DIM / 4) {
        float4 a = *(const float4*)(A + (size_t)row * IN_DIM + q * 4);
        h0 = __floats2half2_rn(a.x, a.y);
        h1 = __floats2half2_rn(a.z, a.w);
    } else {
        h0 = __floats2half2_rn(0.f, 0.f);
        h1 = h0;
    }
    *(uint2*)(Ah + (size_t)row * K_PAD + q * 4) =
        make_uint2(*(const uint32_t*)&h0, *(const uint32_t*)&h1);
}

// -------------------- Kernel 0b: transpose W0 -> [n][k] fp16 ----------------
__global__ void convB_kernel(const float* __restrict__ W,
                             __half* __restrict__ hi)
{
    __shared__ float tile[32][33];
    int k0 = blockIdx.x * 32;
    int n0 = blockIdx.y * 32;
    int tx = threadIdx.x, ty = threadIdx.y;   // block (32, 8)
#pragma unroll
    for (int r = 0; r < 4; r++) {
        int kk = ty + r * 8;
        int k  = k0 + kk;
        tile[kk][tx] = (k < IN_DIM) ? W[(size_t)k * HID + n0 + tx] : 0.0f;
    }
    __syncthreads();
#pragma unroll
    for (int r = 0; r < 4; r++) {
        int nn = ty + r * 8;
        hi[(size_t)(n0 + nn) * K_PAD + k0 + tx] = __float2half(tile[tx][nn]);
    }
}

// -------------------- Kernel 0c: transpose W1 -> W1t[30][512] ---------------
__global__ void convW1_kernel(const float* __restrict__ W1,
                              float* __restrict__ W1t)
{
    for (int i = threadIdx.x; i < LAT * HID; i += 256) {
        int k = i / HID;
        int d = i % HID;
        W1t[i] = W1[d * LAT + k];
    }
}

// -------------------- Kernel 1: fp16 warp-MMA GEMM (R9 config) --------------
__device__ __forceinline__ void ldg_chunk(uint32_t base, int k0, int t,
                                          const __half* Ah, const __half* Bh)
{
#pragma unroll
    for (int i = 0; i < 2; i++) {
        int lin = t + i * 512;
        int row = lin >> 3, seg = lin & 7;
        uint32_t so = sw128((uint32_t)(row * 128 + seg * 16));
        cp_async16(base + so, Ah + (size_t)row * K_PAD + k0 + seg * 8);
    }
#pragma unroll
    for (int i = 0; i < 4; i++) {
        int lin = t + i * 512;
        int row = lin >> 3, seg = lin & 7;
        uint32_t so = sw128((uint32_t)(row * 128 + seg * 16));
        cp_async16(base + A_BYTES + so, Bh + (size_t)row * K_PAD + k0 + seg * 8);
    }
}

__global__ __launch_bounds__(512, 1)
void gemm_mma_kernel(__half* __restrict__ Xout)
{
    extern __shared__ __align__(1024) char smem[];
    const uint32_t sb = smem_u32(smem);
    const int t    = threadIdx.x;
    const int wid  = t >> 5;
    const int lane = t & 31;
    const int wy   = wid >> 2;
    const int wx   = wid & 3;

    const __half* Ah = g_Ah  + (size_t)(blockIdx.y * BM) * K_PAD;
    const __half* Bh = g_Bhi + (size_t)(blockIdx.x * BN) * K_PAD;

    float acc[2][8][4];
#pragma unroll
    for (int i = 0; i < 2; i++)
#pragma unroll
        for (int j = 0; j < 8; j++)
#pragma unroll
            for (int q = 0; q < 4; q++) acc[i][j][q] = 0.0f;

    const int a_row = (lane & 15);
    const int a_k8  = (lane >> 4);
    const int b_row = ((lane >> 4) << 3) + (lane & 7);
    const int b_k8  = (lane >> 3) & 1;

#pragma unroll
    for (int s = 0; s < NSTAGE - 1; s++) {
        ldg_chunk(sb + s * STAGE, s * BK, t, Ah, Bh);
        cp_commit();
    }

    for (int c = 0; c < NCHUNK; c++) {
        asm volatile("cp.async.wait_group %0;" :: "n"(NSTAGE - 2) : "memory");
        __syncthreads();

        if (c + NSTAGE - 1 < NCHUNK)
            ldg_chunk(sb + ((c + NSTAGE - 1) % NSTAGE) * STAGE,
                      (c + NSTAGE - 1) * BK, t, Ah, Bh);
        cp_commit();

        const uint32_t base = sb + (c % NSTAGE) * STAGE;
        const uint32_t aH = base;
        const uint32_t bH = base + A_BYTES;

#pragma unroll
        for (int kk = 0; kk < 4; kk++) {
            uint32_t ah[2][4];
#pragma unroll
            for (int mt = 0; mt < 2; mt++) {
                int row = wy * 32 + mt * 16 + a_row;
                int kcol = kk * 16 + a_k8 * 8;
                uint32_t off = sw128((uint32_t)(row * 128 + kcol * 2));
                ldmx4(ah[mt], aH + off);
            }
#pragma unroll
            for (int ng = 0; ng < 4; ng++) {
                int n = wx * 64 + ng * 16 + b_row;
                int kcol = kk * 16 + b_k8 * 8;
                uint32_t off = sw128((uint32_t)(n * 128 + kcol * 2));
                uint32_t bh[4];
                ldmx4(bh, bH + off);
#pragma unroll
                for (int mt = 0; mt < 2; mt++) {
                    mma_fp16(acc[mt][2 * ng],     ah[mt], bh);
                    mma_fp16(acc[mt][2 * ng + 1], ah[mt], bh + 2);
                }
            }
        }
        __syncthreads();
    }

    __half* dst = Xout + (size_t)(blockIdx.y * BM + wy * 32) * HID
                + blockIdx.x * BN + wx * 64;
    const int r0 = lane >> 2;
    const int c0 = (lane & 3) * 2;
#pragma unroll
    for (int mt = 0; mt < 2; mt++) {
#pragma unroll
        for (int nt = 0; nt < 8; nt++) {
            __half2 h01 = __floats2half2_rn(acc[mt][nt][0], acc[mt][nt][1]);
            __half2 h23 = __floats2half2_rn(acc[mt][nt][2], acc[mt][nt][3]);
            *(__half2*)(dst + (size_t)(mt * 16 + r0) * HID + nt * 8 + c0) = h01;
            *(__half2*)(dst + (size_t)(mt * 16 + r0 + 8) * HID + nt * 8 + c0) = h23;
        }
    }
}

// -------------------- Kernel 2: f0 = X@v0, f1 = X@v1 (fp16 X) ---------------
__global__ void fvec_kernel(const __half* __restrict__ Xh,
                            const float* __restrict__ v0,
                            const float* __restrict__ v1,
                            float* __restrict__ f0, float* __restrict__ f1)
{
    int row  = blockIdx.x * 8 + (threadIdx.x >> 5);
    int lane = threadIdx.x & 31;
    const uint4* xr = (const uint4*)(Xh + (size_t)row * HID);
    const float4* w0 = (const float4*)v0;
    const float4* w1 = (const float4*)v1;
    float s0 = 0.f, s1 = 0.f;
#pragma unroll
    for (int i = 0; i < 2; i++) {
        int u = lane + i * 32;
        uint4 xv = xr[u];
        const __half2* xp = (const __half2*)&xv;
#pragma unroll
        for (int p = 0; p < 2; p++) {
            float2 e0 = __half22float2(xp[p * 2 + 0]);
            float2 e1 = __half22float2(xp[p * 2 + 1]);
            float4 a = w0[u * 2 + p];
            float4 b = w1[u * 2 + p];
            s0 += e0.x * a.x + e0.y * a.y + e1.x * a.z + e1.y * a.w;
            s1 += e0.x * b.x + e0.y * b.y + e1.x * b.z + e1.y * b.w;
        }
    }
#pragma unroll
    for (int o = 16; o > 0; o >>= 1) {
        s0 += __shfl_xor_sync(0xffffffffu, s0, o);
        s1 += __shfl_xor_sync(0xffffffffu, s1, o);
    }
    if (lane == 0) { f0[row] = s0; f1[row] = s1; }
}

// -------------------- Kernel 3: sparsify graph rows -------------------------
__global__ __launch_bounds__(512)
void sparsify_kernel(const float* __restrict__ graph,
                     int* __restrict__ idx, int* __restrict__ cnt)
{
    int row = blockIdx.x;
    __shared__ int c;
    if (threadIdx.x == 0) c = 0;
    __syncthreads();
    const float4* g = (const float4*)(graph + (size_t)row * M_N);
    const int t = threadIdx.x;
    float4 v[4];
#pragma unroll
    for (int i = 0; i < 4; i++) v[i] = __ldg(&g[t + i * 512]);
#pragma unroll
    for (int i = 0; i < 4; i++) {
        int b = (t + i * 512) * 4;
        if (v[i].x != 0.0f) { int s = atomicAdd(&c, 1); if (s < MAXD) idx[row * MAXD + s] = b + 0; }
        if (v[i].y != 0.0f) { int s = atomicAdd(&c, 1); if (s < MAXD) idx[row * MAXD + s] = b + 1; }
        if (v[i].z != 0.0f) { int s = atomicAdd(&c, 1); if (s < MAXD) idx[row * MAXD + s] = b + 2; }
        if (v[i].w != 0.0f) { int s = atomicAdd(&c, 1); if (s < MAXD) idx[row * MAXD + s] = b + 3; }
    }
    __syncthreads();
    if (threadIdx.x == 0) cnt[row] = (c < MAXD) ? c : MAXD;
}

// -------------------- Kernel 4: attention + aggregation + ELU + W1 ----------
// Block-per-row (R9 structure). W1 phase uses transposed W1t with float4
// loads: 16 LDG.128(L1) + 16 LDS.128 per thread instead of 128 scalar loads.
__global__ __launch_bounds__(256)
void attn_kernel(const __half* __restrict__ Xh,
                 const float* __restrict__ f0, const float* __restrict__ f1,
                 const float* __restrict__ W1t,
                 const int* __restrict__ idx, const int* __restrict__ cnt,
                 float* __restrict__ out)
{
    const int row = blockIdx.x;
    const int t   = threadIdx.x;

    __shared__ __align__(16) float s_hq[4 * HID];
    __shared__ __align__(16) float s_h[HID];
    __shared__ __align__(16) float s_e[MAXD];
    __shared__ __align__(16) float s_part[8][32];
    __shared__ int   s_idx[MAXD];
    __shared__ float s_inv;

    const int n = cnt[row];              // 1..MAXD (self loop guarantees >=1)

    if (t < n) {
        int id = idx[row * MAXD + t];
        s_idx[t] = id;
        float e   = f0[row] + f1[id];
        float sig = 1.0f / (1.0f + __expf(-e));
        s_e[t] = __expf(sig - 0.5f);
    }
    __syncthreads();

    if (t < 32) {
        float s = 0.0f;
        for (int j = t; j < n; j += 32) s += s_e[j];
#pragma unroll
        for (int o = 16; o > 0; o >>= 1) s += __shfl_xor_sync(0xffffffffu, s, o);
        if (t == 0) s_inv = 1.0f / fmaxf(s, 1e-30f);
    }
    __syncthreads();
    const float inv = s_inv;

    // aggregation: quarter q handles neighbors j ≡ q (mod 4), unrolled x4
    const int q = t >> 6;
    const int u = t & 63;
    float acc[8];
#pragma unroll
    for (int i = 0; i < 8; i++) acc[i] = 0.0f;

    int j = q;
    for (; j + 12 < n; j += 16) {
        float a0 = s_e[j] * inv,      a1 = s_e[j + 4] * inv;
        float a2 = s_e[j + 8] * inv,  a3 = s_e[j + 12] * inv;
        uint4 x0 = *((const uint4*)(Xh + (size_t)s_idx[j]      * HID) + u);
        uint4 x1 = *((const uint4*)(Xh + (size_t)s_idx[j + 4]  * HID) + u);
        uint4 x2 = *((const uint4*)(Xh + (size_t)s_idx[j + 8]  * HID) + u);
        uint4 x3 = *((const uint4*)(Xh + (size_t)s_idx[j + 12] * HID) + u);
        const __half2* p0 = (const __half2*)&x0;
        const __half2* p1 = (const __half2*)&x1;
        const __half2* p2 = (const __half2*)&x2;
        const __half2* p3 = (const __half2*)&x3;
#pragma unroll
        for (int p = 0; p < 4; p++) {
            float2 fa = __half22float2(p0[p]);
            float2 fb = __half22float2(p1[p]);
            float2 fc = __half22float2(p2[p]);
            float2 fd = __half22float2(p3[p]);
            acc[2 * p]     += a0 * fa.x + a1 * fb.x + a2 * fc.x + a3 * fd.x;
            acc[2 * p + 1] += a0 * fa.y + a1 * fb.y + a2 * fc.y + a3 * fd.y;
        }
    }
    for (; j < n; j += 4) {
        const float a0 = s_e[j] * inv;
        const uint4 xv = *((const uint4*)(Xh + (size_t)s_idx[j] * HID) + u);
        const __half2* p0 = (const __half2*)&xv;
#pragma unroll
        for (int p = 0; p < 4; p++) {
            float2 fa = __half22float2(p0[p]);
            acc[2 * p]     += a0 * fa.x;
            acc[2 * p + 1] += a0 * fa.y;
        }
    }
    ((float4*)(s_hq + q * HID))[u * 2] =
        make_float4(acc[0], acc[1], acc[2], acc[3]);
    ((float4*)(s_hq + q * HID))[u * 2 + 1] =
        make_float4(acc[4], acc[5], acc[6], acc[7]);
    __syncthreads();

    if (t < 128) {
        float4 r = make_float4(0.f, 0.f, 0.f, 0.f);
#pragma unroll
        for (int qq = 0; qq < 4; qq++) {
            float4 v = ((const float4*)s_hq)[qq * 128 + t];
            r.x += v.x; r.y += v.y; r.z += v.z; r.w += v.w;
        }
        r.x = (r.x > 0.f) ? r.x : expm1f(r.x);
        r.y = (r.y > 0.f) ? r.y : expm1f(r.y);
        r.z = (r.z > 0.f) ? r.z : expm1f(r.z);
        r.w = (r.w > 0.f) ? r.w : expm1f(r.w);
        ((float4*)s_h)[t] = r;
    }
    __syncthreads();

    // W1 projection via transposed W1t: contiguous float4 loads per thread.
    if (t < 240) {
        int k  = t % 30;
        int sl = t / 30;
        const int d0 = sl * 64;
        const float4* h4 = (const float4*)(s_h + d0);
        const float4* w4 = (const float4*)(W1t + k * HID + d0);
        float p0 = 0.f, p1 = 0.f, p2 = 0.f, p3 = 0.f;
#pragma unroll
        for (int i = 0; i < 16; i += 4) {
            float4 ha = h4[i],     wa = __ldg(&w4[i]);
            float4 hb = h4[i + 1], wb = __ldg(&w4[i + 1]);
            float4 hc = h4[i + 2], wc = __ldg(&w4[i + 2]);
            float4 hd = h4[i + 3], wd = __ldg(&w4[i + 3]);
            p0 += ha.x * wa.x + ha.y * wa.y + ha.z * wa.z + ha.w * wa.w;
            p1 += hb.x * wb.x + hb.y * wb.y + hb.z * wb.z + hb.w * wb.w;
            p2 += hc.x * wc.x + hc.y * wc.y + hc.z * wc.z + hc.w * wc.w;
            p3 += hd.x * wd.x + hd.y * wd.y + hd.z * wd.z + hd.w * wd.w;
        }
        s_part[sl][k] = (p0 + p1) + (p2 + p3);
    }
    __syncthreads();
    if (t < LAT) {
        float r = 0.0f;
#pragma unroll
        for (int sl = 0; sl < 8; sl++) r += s_part[sl][t];
        out[(size_t)row * LAT + t] = r;
    }
}

// -------------------- launch -------------------------------------------------
extern "C" void kernel_launch(void* const* d_in, const int* in_sizes, int n_in,
                              void* d_out, int out_size)
{
    const float* node_features = (const float*)d_in[0]; // [8192,3000]
    const float* graph         = (const float*)d_in[1]; // [8192,8192]
    const float* W0            = (const float*)d_in[2]; // [3000,512]
    const float* v0            = (const float*)d_in[3]; // [512]
    const float* v1            = (const float*)d_in[4]; // [512]
    const float* W1            = (const float*)d_in[5]; // [512,30]
    float* out = (float*)d_out;

    __half *Ah, *Xh, *Bhi;
    float *f0, *f1, *W1t;
    int *idx, *cnt;
    cudaGetSymbolAddress((void**)&Ah,  g_Ah);
    cudaGetSymbolAddress((void**)&Xh,  g_Xh);
    cudaGetSymbolAddress((void**)&f0,  g_f0);
    cudaGetSymbolAddress((void**)&f1,  g_f1);
    cudaGetSymbolAddress((void**)&idx, g_idx);
    cudaGetSymbolAddress((void**)&cnt, g_cnt);
    cudaGetSymbolAddress((void**)&Bhi, g_Bhi);
    cudaGetSymbolAddress((void**)&W1t, g_W1t);

    static cudaStream_t s2 = nullptr;
    static cudaEvent_t evFork = nullptr, evB = nullptr, evJoin = nullptr;
    if (s2 == nullptr) {
        cudaStreamCreateWithFlags(&s2, cudaStreamNonBlocking);
        cudaEventCreateWithFlags(&evFork, cudaEventDisableTiming);
        cudaEventCreateWithFlags(&evB,    cudaEventDisableTiming);
        cudaEventCreateWithFlags(&evJoin, cudaEventDisableTiming);
        cudaFuncSetAttribute(gemm_mma_kernel,
                             cudaFuncAttributeMaxDynamicSharedMemorySize,
                             SMEM_TOTAL);
    }

    // fork: convB, W1 transpose, then sparsify on s2; convA concurrent on main
    cudaEventRecord(evFork, 0);
    cudaStreamWaitEvent(s2, evFork, 0);
    convB_kernel<<<dim3(K_PAD / 32, HID / 32), dim3(32, 8), 0, s2>>>(W0, Bhi);
    convW1_kernel<<<1, 256, 0, s2>>>(W1, W1t);
    cudaEventRecord(evB, s2);
    sparsify_kernel<<<M_N, 512, 0, s2>>>(graph, idx, cnt);
    cudaEventRecord(evJoin, s2);

    // main chain
    convA_kernel<<<dim3(3, M_N), 256>>>(node_features, Ah);
    cudaStreamWaitEvent(0, evB, 0);
    gemm_mma_kernel<<<dim3(HID / BN, M_N / BM), 512, SMEM_TOTAL>>>(Xh);
    fvec_kernel<<<M_N / 8, 256>>>(Xh, v0, v1, f0, f1);

    // join: attn needs both the GEMM chain and sparsify
    cudaStreamWaitEvent(0, evJoin, 0);
    attn_kernel<<<M_N, 256>>>(Xh, f0, f1, W1t, idx, cnt, out);
}

// round 15
// speedup vs baseline: 1.4477x; 1.4477x over previous
#include <cuda_runtime.h>
#include <cuda_fp16.h>
#include <math.h>
#include <stdint.h>

// -------------------- problem constants --------------------
#define M_N     8192
#define IN_DIM  3000
#define K_PAD   3008        // 47 * 64
#define HID     512
#define LAT     30
#define MAXD    192

#define BM      128
#define BN      256
#define BK      64
#define NCHUNK  (K_PAD / BK)   // 47
#define NSTAGE  4

// SMEM stage layout (bytes): Ah[128x64]=16K, Bh[256x64]=32K
#define A_BYTES   16384
#define B_BYTES   32768
#define STAGE     (A_BYTES + B_BYTES)            // 49152
#define SMEM_TOTAL (NSTAGE * STAGE)              // 196608

// -------------------- static device scratch --------------------
__device__ __align__(16) __half g_Ah[(size_t)M_N * K_PAD];    // 49 MB fp16 A
__device__ __align__(16) __half g_Xh[(size_t)M_N * HID];      // 8 MB fp16 X
__device__ float g_f0[M_N];
__device__ float g_f1[M_N];
__device__ int   g_idx[M_N * MAXD];
__device__ int   g_cnt[M_N];
__device__ __align__(16) __half g_Bhi[(size_t)HID * K_PAD];   // [n][k] fp16

// -------------------- PTX helpers --------------------
__device__ __forceinline__ uint32_t smem_u32(const void* p) {
    uint32_t a;
    asm("{ .reg .u64 t; cvta.to.shared.u64 t, %1; cvt.u32.u64 %0, t; }"
        : "=r"(a) : "l"(p));
    return a;
}

__device__ __forceinline__ uint32_t sw128(uint32_t off) {
    return off ^ ((off >> 3) & 0x70);
}

__device__ __forceinline__ void cp_async16(uint32_t dst, const void* src) {
    asm volatile("cp.async.cg.shared.global [%0], [%1], 16;"
                 :: "r"(dst), "l"(src));
}
__device__ __forceinline__ void cp_commit() {
    asm volatile("cp.async.commit_group;" ::: "memory");
}

__device__ __forceinline__ void ldmx4(uint32_t* r, uint32_t addr) {
    asm volatile("ldmatrix.sync.aligned.m8n8.x4.shared.b16 {%0,%1,%2,%3}, [%4];"
                 : "=r"(r[0]), "=r"(r[1]), "=r"(r[2]), "=r"(r[3]) : "r"(addr));
}

__device__ __forceinline__ void mma_fp16(float* d, const uint32_t* a,
                                         const uint32_t* b) {
    asm volatile(
        "mma.sync.aligned.m16n8k16.row.col.f32.f16.f16.f32 "
        "{%0,%1,%2,%3}, {%4,%5,%6,%7}, {%8,%9}, {%0,%1,%2,%3};"
        : "+f"(d[0]), "+f"(d[1]), "+f"(d[2]), "+f"(d[3])
        : "r"(a[0]), "r"(a[1]), "r"(a[2]), "r"(a[3]), "r"(b[0]), "r"(b[1]));
}

// -------------------- Kernel 0a: A fp32 -> fp16 (padded K) ------------------
__global__ __launch_bounds__(256)
void convA_kernel(const float* __restrict__ A, __half* __restrict__ Ah)
{
    const int row = blockIdx.y;
    const int q   = blockIdx.x * 256 + threadIdx.x;
    if (q >= K_PAD / 4) return;
    __half2 h0, h1;
    if (q < IN_DIM / 4) {
        float4 a = *(const float4*)(A + (size_t)row * IN_DIM + q * 4);
        h0 = __floats2half2_rn(a.x, a.y);
        h1 = __floats2half2_rn(a.z, a.w);
    } else {
        h0 = __floats2half2_rn(0.f, 0.f);
        h1 = h0;
    }
    *(uint2*)(Ah + (size_t)row * K_PAD + q * 4) =
        make_uint2(*(const uint32_t*)&h0, *(const uint32_t*)&h1);
}

// -------------------- Kernel 0b: transpose W0 -> [n][k] fp16 ----------------
__global__ void convB_kernel(const float* __restrict__ W,
                             __half* __restrict__ hi)
{
    __shared__ float tile[32][33];
    int k0 = blockIdx.x * 32;
    int n0 = blockIdx.y * 32;
    int tx = threadIdx.x, ty = threadIdx.y;   // block (32, 8)
#pragma unroll
    for (int r = 0; r < 4; r++) {
        int kk = ty + r * 8;
        int k  = k0 + kk;
        tile[kk][tx] = (k < IN_DIM) ? W[(size_t)k * HID + n0 + tx] : 0.0f;
    }
    __syncthreads();
#pragma unroll
    for (int r = 0; r < 4; r++) {
        int nn = ty + r * 8;
        hi[(size_t)(n0 + nn) * K_PAD + k0 + tx] = __float2half(tile[tx][nn]);
    }
}

// -------------------- Kernel 1: fp16 warp-MMA GEMM + fused f0/f1 ------------
__device__ __forceinline__ void ldg_chunk(uint32_t base, int k0, int t,
                                          const __half* Ah, const __half* Bh)
{
#pragma unroll
    for (int i = 0; i < 2; i++) {
        int lin = t + i * 512;
        int row = lin >> 3, seg = lin & 7;
        uint32_t so = sw128((uint32_t)(row * 128 + seg * 16));
        cp_async16(base + so, Ah + (size_t)row * K_PAD + k0 + seg * 8);
    }
#pragma unroll
    for (int i = 0; i < 4; i++) {
        int lin = t + i * 512;
        int row = lin >> 3, seg = lin & 7;
        uint32_t so = sw128((uint32_t)(row * 128 + seg * 16));
        cp_async16(base + A_BYTES + so, Bh + (size_t)row * K_PAD + k0 + seg * 8);
    }
}

__global__ __launch_bounds__(512, 1)
void gemm_mma_kernel(__half* __restrict__ Xout,
                     const float* __restrict__ v0,
                     const float* __restrict__ v1,
                     float* __restrict__ f0, float* __restrict__ f1)
{
    extern __shared__ __align__(1024) char smem[];
    const uint32_t sb = smem_u32(smem);
    const int t    = threadIdx.x;
    const int wid  = t >> 5;
    const int lane = t & 31;
    const int wy   = wid >> 2;
    const int wx   = wid & 3;

    const __half* Ah = g_Ah  + (size_t)(blockIdx.y * BM) * K_PAD;
    const __half* Bh = g_Bhi + (size_t)(blockIdx.x * BN) * K_PAD;

    float acc[2][8][4];
#pragma unroll
    for (int i = 0; i < 2; i++)
#pragma unroll
        for (int j = 0; j < 8; j++)
#pragma unroll
            for (int q = 0; q < 4; q++) acc[i][j][q] = 0.0f;

    const int a_row = (lane & 15);
    const int a_k8  = (lane >> 4);
    const int b_row = ((lane >> 4) << 3) + (lane & 7);
    const int b_k8  = (lane >> 3) & 1;

#pragma unroll
    for (int s = 0; s < NSTAGE - 1; s++) {
        ldg_chunk(sb + s * STAGE, s * BK, t, Ah, Bh);
        cp_commit();
    }

    for (int c = 0; c < NCHUNK; c++) {
        asm volatile("cp.async.wait_group %0;" :: "n"(NSTAGE - 2) : "memory");
        __syncthreads();

        if (c + NSTAGE - 1 < NCHUNK)
            ldg_chunk(sb + ((c + NSTAGE - 1) % NSTAGE) * STAGE,
                      (c + NSTAGE - 1) * BK, t, Ah, Bh);
        cp_commit();

        const uint32_t base = sb + (c % NSTAGE) * STAGE;
        const uint32_t aH = base;
        const uint32_t bH = base + A_BYTES;

#pragma unroll
        for (int kk = 0; kk < 4; kk++) {
            uint32_t ah[2][4];
#pragma unroll
            for (int mt = 0; mt < 2; mt++) {
                int row = wy * 32 + mt * 16 + a_row;
                int kcol = kk * 16 + a_k8 * 8;
                uint32_t off = sw128((uint32_t)(row * 128 + kcol * 2));
                ldmx4(ah[mt], aH + off);
            }
#pragma unroll
            for (int ng = 0; ng < 4; ng++) {
                int n = wx * 64 + ng * 16 + b_row;
                int kcol = kk * 16 + b_k8 * 8;
                uint32_t off = sw128((uint32_t)(n * 128 + kcol * 2));
                uint32_t bh[4];
                ldmx4(bh, bH + off);
#pragma unroll
                for (int mt = 0; mt < 2; mt++) {
                    mma_fp16(acc[mt][2 * ng],     ah[mt], bh);
                    mma_fp16(acc[mt][2 * ng + 1], ah[mt], bh + 2);
                }
            }
        }
        __syncthreads();
    }

    // epilogue: write fp16 X and fused f0/f1 partial dot products
    const int colbase = blockIdx.x * BN + wx * 64;
    __half* dst = Xout + (size_t)(blockIdx.y * BM + wy * 32) * HID + colbase;
    const int r0 = lane >> 2;
    const int c0 = (lane & 3) * 2;

#pragma unroll
    for (int mt = 0; mt < 2; mt++) {
        float d0 = 0.0f, d1 = 0.0f;   // partial dots for row (mt*16 + r0)
        float e0 = 0.0f, e1 = 0.0f;   // partial dots for row (mt*16 + r0 + 8)
#pragma unroll
        for (int nt = 0; nt < 8; nt++) {
            __half2 h01 = __floats2half2_rn(acc[mt][nt][0], acc[mt][nt][1]);
            __half2 h23 = __floats2half2_rn(acc[mt][nt][2], acc[mt][nt][3]);
            *(__half2*)(dst + (size_t)(mt * 16 + r0) * HID + nt * 8 + c0) = h01;
            *(__half2*)(dst + (size_t)(mt * 16 + r0 + 8) * HID + nt * 8 + c0) = h23;
            // fvec partials (use the exact fp16-rounded values for consistency)
            float2 w0v = *(const float2*)(v0 + colbase + nt * 8 + c0);
            float2 w1v = *(const float2*)(v1 + colbase + nt * 8 + c0);
            float2 x01 = __half22float2(h01);
            float2 x23 = __half22float2(h23);
            d0 += x01.x * w0v.x + x01.y * w0v.y;
            d1 += x01.x * w1v.x + x01.y * w1v.y;
            e0 += x23.x * w0v.x + x23.y * w0v.y;
            e1 += x23.x * w1v.x + x23.y * w1v.y;
        }
        // reduce across the 4 lanes sharing a row (lane = r0*4 + g, g=0..3)
#pragma unroll
        for (int o = 2; o > 0; o >>= 1) {
            d0 += __shfl_xor_sync(0xffffffffu, d0, o);
            d1 += __shfl_xor_sync(0xffffffffu, d1, o);
            e0 += __shfl_xor_sync(0xffffffffu, e0, o);
            e1 += __shfl_xor_sync(0xffffffffu, e1, o);
        }
        if ((lane & 3) == 0) {
            int rowA = blockIdx.y * BM + wy * 32 + mt * 16 + r0;
            atomicAdd(&f0[rowA], d0);
            atomicAdd(&f1[rowA], d1);
            atomicAdd(&f0[rowA + 8], e0);
            atomicAdd(&f1[rowA + 8], e1);
        }
    }
}

// -------------------- Kernel 3: sparsify graph rows -------------------------
__global__ __launch_bounds__(512)
void sparsify_kernel(const float* __restrict__ graph,
                     int* __restrict__ idx, int* __restrict__ cnt)
{
    int row = blockIdx.x;
    __shared__ int c;
    if (threadIdx.x == 0) c = 0;
    __syncthreads();
    const float4* g = (const float4*)(graph + (size_t)row * M_N);
    const int t = threadIdx.x;
    float4 v[4];
#pragma unroll
    for (int i = 0; i < 4; i++) v[i] = __ldg(&g[t + i * 512]);
#pragma unroll
    for (int i = 0; i < 4; i++) {
        int b = (t + i * 512) * 4;
        if (v[i].x != 0.0f) { int s = atomicAdd(&c, 1); if (s < MAXD) idx[row * MAXD + s] = b + 0; }
        if (v[i].y != 0.0f) { int s = atomicAdd(&c, 1); if (s < MAXD) idx[row * MAXD + s] = b + 1; }
        if (v[i].z != 0.0f) { int s = atomicAdd(&c, 1); if (s < MAXD) idx[row * MAXD + s] = b + 2; }
        if (v[i].w != 0.0f) { int s = atomicAdd(&c, 1); if (s < MAXD) idx[row * MAXD + s] = b + 3; }
    }
    __syncthreads();
    if (threadIdx.x == 0) cnt[row] = (c < MAXD) ? c : MAXD;
}

// -------------------- Kernel 4: attention + aggregation + ELU + W1 ----------
// Block-per-row (exact R9 structure; W1 accessed in its original layout —
// consecutive k across lanes = coalesced).
__global__ __launch_bounds__(256)
void attn_kernel(const __half* __restrict__ Xh,
                 const float* __restrict__ f0, const float* __restrict__ f1,
                 const float* __restrict__ W1,
                 const int* __restrict__ idx, const int* __restrict__ cnt,
                 float* __restrict__ out)
{
    const int row = blockIdx.x;
    const int t   = threadIdx.x;

    __shared__ __align__(16) float s_hq[4 * HID];
    __shared__ __align__(16) float s_h[HID];
    __shared__ __align__(16) float s_e[MAXD];
    __shared__ __align__(16) float s_part[8][32];
    __shared__ int   s_idx[MAXD];
    __shared__ float s_inv;

    const int n = cnt[row];              // 1..MAXD (self loop guarantees >=1)

    if (t < n) {
        int id = idx[row * MAXD + t];
        s_idx[t] = id;
        float e   = f0[row] + f1[id];
        float sig = 1.0f / (1.0f + __expf(-e));
        s_e[t] = __expf(sig - 0.5f);
    }
    __syncthreads();

    if (t < 32) {
        float s = 0.0f;
        for (int j = t; j < n; j += 32) s += s_e[j];
#pragma unroll
        for (int o = 16; o > 0; o >>= 1) s += __shfl_xor_sync(0xffffffffu, s, o);
        if (t == 0) s_inv = 1.0f / fmaxf(s, 1e-30f);
    }
    __syncthreads();
    const float inv = s_inv;

    // aggregation: quarter q handles neighbors j ≡ q (mod 4), unrolled x4
    const int q = t >> 6;
    const int u = t & 63;
    float acc[8];
#pragma unroll
    for (int i = 0; i < 8; i++) acc[i] = 0.0f;

    int j = q;
    for (; j + 12 < n; j += 16) {
        float a0 = s_e[j] * inv,      a1 = s_e[j + 4] * inv;
        float a2 = s_e[j + 8] * inv,  a3 = s_e[j + 12] * inv;
        uint4 x0 = *((const uint4*)(Xh + (size_t)s_idx[j]      * HID) + u);
        uint4 x1 = *((const uint4*)(Xh + (size_t)s_idx[j + 4]  * HID) + u);
        uint4 x2 = *((const uint4*)(Xh + (size_t)s_idx[j + 8]  * HID) + u);
        uint4 x3 = *((const uint4*)(Xh + (size_t)s_idx[j + 12] * HID) + u);
        const __half2* p0 = (const __half2*)&x0;
        const __half2* p1 = (const __half2*)&x1;
        const __half2* p2 = (const __half2*)&x2;
        const __half2* p3 = (const __half2*)&x3;
#pragma unroll
        for (int p = 0; p < 4; p++) {
            float2 fa = __half22float2(p0[p]);
            float2 fb = __half22float2(p1[p]);
            float2 fc = __half22float2(p2[p]);
            float2 fd = __half22float2(p3[p]);
            acc[2 * p]     += a0 * fa.x + a1 * fb.x + a2 * fc.x + a3 * fd.x;
            acc[2 * p + 1] += a0 * fa.y + a1 * fb.y + a2 * fc.y + a3 * fd.y;
        }
    }
    for (; j < n; j += 4) {
        const float a0 = s_e[j] * inv;
        const uint4 xv = *((const uint4*)(Xh + (size_t)s_idx[j] * HID) + u);
        const __half2* p0 = (const __half2*)&xv;
#pragma unroll
        for (int p = 0; p < 4; p++) {
            float2 fa = __half22float2(p0[p]);
            acc[2 * p]     += a0 * fa.x;
            acc[2 * p + 1] += a0 * fa.y;
        }
    }
    ((float4*)(s_hq + q * HID))[u * 2] =
        make_float4(acc[0], acc[1], acc[2], acc[3]);
    ((float4*)(s_hq + q * HID))[u * 2 + 1] =
        make_float4(acc[4], acc[5], acc[6], acc[7]);
    __syncthreads();

    if (t < 128) {
        float4 r = make_float4(0.f, 0.f, 0.f, 0.f);
#pragma unroll
        for (int qq = 0; qq < 4; qq++) {
            float4 v = ((const float4*)s_hq)[qq * 128 + t];
            r.x += v.x; r.y += v.y; r.z += v.z; r.w += v.w;
        }
        r.x = (r.x > 0.f) ? r.x : (__expf(r.x) - 1.0f);
        r.y = (r.y > 0.f) ? r.y : (__expf(r.y) - 1.0f);
        r.z = (r.z > 0.f) ? r.z : (__expf(r.z) - 1.0f);
        r.w = (r.w > 0.f) ? r.w : (__expf(r.w) - 1.0f);
        ((float4*)s_h)[t] = r;
    }
    __syncthreads();

    if (t < 240) {
        int k  = t % 30;
        int sl = t / 30;
        float p = 0.0f;
        const int d0 = sl * 64;
#pragma unroll 8
        for (int d = d0; d < d0 + 64; d++) p += s_h[d] * W1[d * LAT + k];
        s_part[sl][k] = p;
    }
    __syncthreads();
    if (t < LAT) {
        float r = 0.0f;
#pragma unroll
        for (int sl = 0; sl < 8; sl++) r += s_part[sl][t];
        out[(size_t)row * LAT + t] = r;
    }
}

// -------------------- launch -------------------------------------------------
extern "C" void kernel_launch(void* const* d_in, const int* in_sizes, int n_in,
                              void* d_out, int out_size)
{
    const float* node_features = (const float*)d_in[0]; // [8192,3000]
    const float* graph         = (const float*)d_in[1]; // [8192,8192]
    const float* W0            = (const float*)d_in[2]; // [3000,512]
    const float* v0            = (const float*)d_in[3]; // [512]
    const float* v1            = (const float*)d_in[4]; // [512]
    const float* W1            = (const float*)d_in[5]; // [512,30]
    float* out = (float*)d_out;

    __half *Ah, *Xh, *Bhi;
    float *f0, *f1;
    int *idx, *cnt;
    cudaGetSymbolAddress((void**)&Ah,  g_Ah);
    cudaGetSymbolAddress((void**)&Xh,  g_Xh);
    cudaGetSymbolAddress((void**)&f0,  g_f0);
    cudaGetSymbolAddress((void**)&f1,  g_f1);
    cudaGetSymbolAddress((void**)&idx, g_idx);
    cudaGetSymbolAddress((void**)&cnt, g_cnt);
    cudaGetSymbolAddress((void**)&Bhi, g_Bhi);

    static cudaStream_t s2 = nullptr;
    static cudaEvent_t evFork = nullptr, evB = nullptr, evJoin = nullptr;
    if (s2 == nullptr) {
        cudaStreamCreateWithFlags(&s2, cudaStreamNonBlocking);
        cudaEventCreateWithFlags(&evFork, cudaEventDisableTiming);
        cudaEventCreateWithFlags(&evB,    cudaEventDisableTiming);
        cudaEventCreateWithFlags(&evJoin, cudaEventDisableTiming);
        cudaFuncSetAttribute(gemm_mma_kernel,
                             cudaFuncAttributeMaxDynamicSharedMemorySize,
                             SMEM_TOTAL);
    }

    // fork: convB then sparsify on s2; convA concurrent on main (R9 layout)
    cudaEventRecord(evFork, 0);
    cudaStreamWaitEvent(s2, evFork, 0);
    convB_kernel<<<dim3(K_PAD / 32, HID / 32), dim3(32, 8), 0, s2>>>(W0, Bhi);
    cudaEventRecord(evB, s2);
    sparsify_kernel<<<M_N, 512, 0, s2>>>(graph, idx, cnt);
    cudaEventRecord(evJoin, s2);

    // main chain
    cudaMemsetAsync(f0, 0, M_N * sizeof(float), 0);
    cudaMemsetAsync(f1, 0, M_N * sizeof(float), 0);
    convA_kernel<<<dim3(3, M_N), 256>>>(node_features, Ah);
    cudaStreamWaitEvent(0, evB, 0);
    gemm_mma_kernel<<<dim3(HID / BN, M_N / BM), 512, SMEM_TOTAL>>>(Xh, v0, v1,
                                                                   f0, f1);

    // join: attn needs both the GEMM chain and sparsify
    cudaStreamWaitEvent(0, evJoin, 0);
    attn_kernel<<<M_N, 256>>>(Xh, f0, f1, W1, idx, cnt, out);
}

// round 16
// speedup vs baseline: 1.5132x; 1.0452x over previous
#include <cuda_runtime.h>
#include <cuda_fp16.h>
#include <math.h>
#include <stdint.h>

// -------------------- problem constants --------------------
#define M_N     8192
#define IN_DIM  3000
#define K_PAD   3008        // 47 * 64
#define HID     512
#define LAT     30
#define MAXD    192

#define BM      128
#define BN      256
#define BK      64
#define NCHUNK  (K_PAD / BK)   // 47

// SMEM stage layout (bytes): Ah[128x64] fp16 = 16K, Bh[256x64] fp16 = 32K
#define A_BYTES   16384
#define B_BYTES   32768
#define STAGE     (A_BYTES + B_BYTES)            // 49152
#define SMEM_TOTAL (2 * STAGE)                   // 98304 (2-stage, R6 config)

// -------------------- static device scratch --------------------
__device__ __align__(16) __half g_Xh[(size_t)M_N * HID];      // 8 MB fp16 X
__device__ float g_f0[M_N];
__device__ float g_f1[M_N];
__device__ int   g_idx[M_N * MAXD];
__device__ int   g_cnt[M_N];
__device__ __align__(16) __half g_Bhi[(size_t)HID * K_PAD];   // [n][k] fp16

// -------------------- PTX helpers --------------------
__device__ __forceinline__ uint32_t smem_u32(const void* p) {
    uint32_t a;
    asm("{ .reg .u64 t; cvta.to.shared.u64 t, %1; cvt.u32.u64 %0, t; }"
        : "=r"(a) : "l"(p));
    return a;
}

__device__ __forceinline__ uint32_t sw128(uint32_t off) {
    return off ^ ((off >> 3) & 0x70);
}

__device__ __forceinline__ void cp_async16(uint32_t dst, const void* src) {
    asm volatile("cp.async.cg.shared.global [%0], [%1], 16;"
                 :: "r"(dst), "l"(src));
}
__device__ __forceinline__ void cp_commit() {
    asm volatile("cp.async.commit_group;" ::: "memory");
}

__device__ __forceinline__ void ldmx4(uint32_t* r, uint32_t addr) {
    asm volatile("ldmatrix.sync.aligned.m8n8.x4.shared.b16 {%0,%1,%2,%3}, [%4];"
                 : "=r"(r[0]), "=r"(r[1]), "=r"(r[2]), "=r"(r[3]) : "r"(addr));
}

__device__ __forceinline__ void mma_fp16(float* d, const uint32_t* a,
                                         const uint32_t* b) {
    asm volatile(
        "mma.sync.aligned.m16n8k16.row.col.f32.f16.f16.f32 "
        "{%0,%1,%2,%3}, {%4,%5,%6,%7}, {%8,%9}, {%0,%1,%2,%3};"
        : "+f"(d[0]), "+f"(d[1]), "+f"(d[2]), "+f"(d[3])
        : "r"(a[0]), "r"(a[1]), "r"(a[2]), "r"(a[3]), "r"(b[0]), "r"(b[1]));
}

// -------------------- Kernel 0: transpose W0 -> [n][k] fp16 -----------------
__global__ void convB_kernel(const float* __restrict__ W,
                             __half* __restrict__ hi)
{
    __shared__ float tile[32][33];
    int k0 = blockIdx.x * 32;
    int n0 = blockIdx.y * 32;
    int tx = threadIdx.x, ty = threadIdx.y;   // block (32, 8)
#pragma unroll
    for (int r = 0; r < 4; r++) {
        int kk = ty + r * 8;
        int k  = k0 + kk;
        tile[kk][tx] = (k < IN_DIM) ? W[(size_t)k * HID + n0 + tx] : 0.0f;
    }
    __syncthreads();
#pragma unroll
    for (int r = 0; r < 4; r++) {
        int nn = ty + r * 8;
        hi[(size_t)(n0 + nn) * K_PAD + k0 + tx] = __float2half(tile[tx][nn]);
    }
}

// -------------------- Kernel 1: fused-A fp16 warp-MMA GEMM (R6 mainloop) ----
// Xh = fp16( A[8192,3000] @ W0 ); A loaded fp32, converted in registers.
// Epilogue also computes f0 = X@v0, f1 = X@v1 via atomics (R15).

__device__ __forceinline__ void ldgA(const float* __restrict__ Abase, int k0,
                                     int t, bool last, float4* v)
{
#pragma unroll
    for (int i = 0; i < 4; i++) {
        int lin = t + i * 512;
        int row = lin >> 4, seg = lin & 15;
        if (last && seg >= 14) {            // cols >= 3000 -> zero pad
            v[i] = make_float4(0.f, 0.f, 0.f, 0.f);
        } else {
            v[i] = *(const float4*)(Abase + (size_t)row * IN_DIM + k0 + seg * 4);
        }
    }
}

__device__ __forceinline__ void stsA(uint32_t base, int t, const float4* v)
{
#pragma unroll
    for (int i = 0; i < 4; i++) {
        int lin = t + i * 512;
        int row = lin >> 4, seg = lin & 15;
        float4 a = v[i];
        __half2 hA = __floats2half2_rn(a.x, a.y);
        __half2 hB = __floats2half2_rn(a.z, a.w);
        uint32_t off = sw128((uint32_t)(row * 128 + seg * 8));
        asm volatile("st.shared.v2.u32 [%0], {%1, %2};"
                     :: "r"(base + off),
                        "r"(*(const uint32_t*)&hA), "r"(*(const uint32_t*)&hB)
                     : "memory");
    }
}

__device__ __forceinline__ void ldgB(uint32_t base, int k0, int t,
                                     const __half* Bh)
{
#pragma unroll
    for (int i = 0; i < 4; i++) {
        int lin = t + i * 512;
        int row = lin >> 3, seg = lin & 7;
        uint32_t so = sw128((uint32_t)(row * 128 + seg * 16));
        cp_async16(base + A_BYTES + so,
                   Bh + (size_t)row * K_PAD + k0 + seg * 8);
    }
}

__global__ __launch_bounds__(512, 1)
void gemm_mma_kernel(const float* __restrict__ A, __half* __restrict__ Xout,
                     const float* __restrict__ v0,
                     const float* __restrict__ v1,
                     float* __restrict__ f0, float* __restrict__ f1)
{
    extern __shared__ __align__(1024) char smem[];
    const uint32_t sb = smem_u32(smem);
    const int t    = threadIdx.x;
    const int wid  = t >> 5;
    const int lane = t & 31;
    const int wy   = wid >> 2;   // 0..3 : m group (32 rows)
    const int wx   = wid & 3;    // 0..3 : n group (64 cols)

    const float* Abase = A + (size_t)(blockIdx.y * BM) * IN_DIM;
    const __half* Bh = g_Bhi + (size_t)(blockIdx.x * BN) * K_PAD;

    float acc[2][8][4];
#pragma unroll
    for (int i = 0; i < 2; i++)
#pragma unroll
        for (int j = 0; j < 8; j++)
#pragma unroll
            for (int q = 0; q < 4; q++) acc[i][j][q] = 0.0f;

    const int a_row = (lane & 15);
    const int a_k8  = (lane >> 4);
    const int b_row = ((lane >> 4) << 3) + (lane & 7);
    const int b_k8  = (lane >> 3) & 1;

    // prologue: chunk 0
    {
        float4 v[4];
        ldgA(Abase, 0, t, false, v);
        stsA(sb, t, v);
        ldgB(sb, 0, t, Bh);
        cp_commit();
    }

    float4 vnext[4];
    for (int c = 0; c < NCHUNK; c++) {
        asm volatile("cp.async.wait_group 0;" ::: "memory");
        __syncthreads();

        const bool pref = (c + 1 < NCHUNK);
        if (pref) {
            ldgA(Abase, (c + 1) * BK, t, (c + 1) == NCHUNK - 1, vnext);
            ldgB(sb + ((c + 1) & 1) * STAGE, (c + 1) * BK, t, Bh);
            cp_commit();
        }

        const uint32_t base = sb + (c & 1) * STAGE;
        const uint32_t aH = base;
        const uint32_t bH = base + A_BYTES;

#pragma unroll
        for (int kk = 0; kk < 4; kk++) {
            uint32_t ah[2][4];
#pragma unroll
            for (int mt = 0; mt < 2; mt++) {
                int row = wy * 32 + mt * 16 + a_row;
                int kcol = kk * 16 + a_k8 * 8;
                uint32_t off = sw128((uint32_t)(row * 128 + kcol * 2));
                ldmx4(ah[mt], aH + off);
            }
#pragma unroll
            for (int ng = 0; ng < 4; ng++) {
                int n = wx * 64 + ng * 16 + b_row;
                int kcol = kk * 16 + b_k8 * 8;
                uint32_t off = sw128((uint32_t)(n * 128 + kcol * 2));
                uint32_t bh[4];
                ldmx4(bh, bH + off);
#pragma unroll
                for (int mt = 0; mt < 2; mt++) {
                    mma_fp16(acc[mt][2 * ng],     ah[mt], bh);
                    mma_fp16(acc[mt][2 * ng + 1], ah[mt], bh + 2);
                }
            }
        }

        if (pref) stsA(sb + ((c + 1) & 1) * STAGE, t, vnext);
        // top-of-loop __syncthreads orders these STS before next compute
    }

    // epilogue: write fp16 X and fused f0/f1 partial dot products
    const int colbase = blockIdx.x * BN + wx * 64;
    __half* dst = Xout + (size_t)(blockIdx.y * BM + wy * 32) * HID + colbase;
    const int r0 = lane >> 2;
    const int c0 = (lane & 3) * 2;

#pragma unroll
    for (int mt = 0; mt < 2; mt++) {
        float d0 = 0.0f, d1 = 0.0f;   // partial dots for row (mt*16 + r0)
        float e0 = 0.0f, e1 = 0.0f;   // partial dots for row (mt*16 + r0 + 8)
#pragma unroll
        for (int nt = 0; nt < 8; nt++) {
            __half2 h01 = __floats2half2_rn(acc[mt][nt][0], acc[mt][nt][1]);
            __half2 h23 = __floats2half2_rn(acc[mt][nt][2], acc[mt][nt][3]);
            *(__half2*)(dst + (size_t)(mt * 16 + r0) * HID + nt * 8 + c0) = h01;
            *(__half2*)(dst + (size_t)(mt * 16 + r0 + 8) * HID + nt * 8 + c0) = h23;
            float2 w0v = *(const float2*)(v0 + colbase + nt * 8 + c0);
            float2 w1v = *(const float2*)(v1 + colbase + nt * 8 + c0);
            float2 x01 = __half22float2(h01);
            float2 x23 = __half22float2(h23);
            d0 += x01.x * w0v.x + x01.y * w0v.y;
            d1 += x01.x * w1v.x + x01.y * w1v.y;
            e0 += x23.x * w0v.x + x23.y * w0v.y;
            e1 += x23.x * w1v.x + x23.y * w1v.y;
        }
#pragma unroll
        for (int o = 2; o > 0; o >>= 1) {
            d0 += __shfl_xor_sync(0xffffffffu, d0, o);
            d1 += __shfl_xor_sync(0xffffffffu, d1, o);
            e0 += __shfl_xor_sync(0xffffffffu, e0, o);
            e1 += __shfl_xor_sync(0xffffffffu, e1, o);
        }
        if ((lane & 3) == 0) {
            int rowA = blockIdx.y * BM + wy * 32 + mt * 16 + r0;
            atomicAdd(&f0[rowA], d0);
            atomicAdd(&f1[rowA], d1);
            atomicAdd(&f0[rowA + 8], e0);
            atomicAdd(&f1[rowA + 8], e1);
        }
    }
}

// -------------------- Kernel 3: sparsify graph rows -------------------------
__global__ __launch_bounds__(512)
void sparsify_kernel(const float* __restrict__ graph,
                     int* __restrict__ idx, int* __restrict__ cnt)
{
    int row = blockIdx.x;
    __shared__ int c;
    if (threadIdx.x == 0) c = 0;
    __syncthreads();
    const float4* g = (const float4*)(graph + (size_t)row * M_N);
    const int t = threadIdx.x;
    float4 v[4];
#pragma unroll
    for (int i = 0; i < 4; i++) v[i] = __ldg(&g[t + i * 512]);
#pragma unroll
    for (int i = 0; i < 4; i++) {
        int b = (t + i * 512) * 4;
        if (v[i].x != 0.0f) { int s = atomicAdd(&c, 1); if (s < MAXD) idx[row * MAXD + s] = b + 0; }
        if (v[i].y != 0.0f) { int s = atomicAdd(&c, 1); if (s < MAXD) idx[row * MAXD + s] = b + 1; }
        if (v[i].z != 0.0f) { int s = atomicAdd(&c, 1); if (s < MAXD) idx[row * MAXD + s] = b + 2; }
        if (v[i].w != 0.0f) { int s = atomicAdd(&c, 1); if (s < MAXD) idx[row * MAXD + s] = b + 3; }
    }
    __syncthreads();
    if (threadIdx.x == 0) cnt[row] = (c < MAXD) ? c : MAXD;
}

// -------------------- Kernel 4: attention + aggregation + ELU + W1 ----------
// Block-per-row (exact R9 structure).
__global__ __launch_bounds__(256)
void attn_kernel(const __half* __restrict__ Xh,
                 const float* __restrict__ f0, const float* __restrict__ f1,
                 const float* __restrict__ W1,
                 const int* __restrict__ idx, const int* __restrict__ cnt,
                 float* __restrict__ out)
{
    const int row = blockIdx.x;
    const int t   = threadIdx.x;

    __shared__ __align__(16) float s_hq[4 * HID];
    __shared__ __align__(16) float s_h[HID];
    __shared__ __align__(16) float s_e[MAXD];
    __shared__ __align__(16) float s_part[8][32];
    __shared__ int   s_idx[MAXD];
    __shared__ float s_inv;

    const int n = cnt[row];              // 1..MAXD (self loop guarantees >=1)

    if (t < n) {
        int id = idx[row * MAXD + t];
        s_idx[t] = id;
        float e   = f0[row] + f1[id];
        float sig = 1.0f / (1.0f + __expf(-e));
        s_e[t] = __expf(sig - 0.5f);
    }
    __syncthreads();

    if (t < 32) {
        float s = 0.0f;
        for (int j = t; j < n; j += 32) s += s_e[j];
#pragma unroll
        for (int o = 16; o > 0; o >>= 1) s += __shfl_xor_sync(0xffffffffu, s, o);
        if (t == 0) s_inv = 1.0f / fmaxf(s, 1e-30f);
    }
    __syncthreads();
    const float inv = s_inv;

    // aggregation: quarter q handles neighbors j ≡ q (mod 4), unrolled x4
    const int q = t >> 6;
    const int u = t & 63;
    float acc[8];
#pragma unroll
    for (int i = 0; i < 8; i++) acc[i] = 0.0f;

    int j = q;
    for (; j + 12 < n; j += 16) {
        float a0 = s_e[j] * inv,      a1 = s_e[j + 4] * inv;
        float a2 = s_e[j + 8] * inv,  a3 = s_e[j + 12] * inv;
        uint4 x0 = *((const uint4*)(Xh + (size_t)s_idx[j]      * HID) + u);
        uint4 x1 = *((const uint4*)(Xh + (size_t)s_idx[j + 4]  * HID) + u);
        uint4 x2 = *((const uint4*)(Xh + (size_t)s_idx[j + 8]  * HID) + u);
        uint4 x3 = *((const uint4*)(Xh + (size_t)s_idx[j + 12] * HID) + u);
        const __half2* p0 = (const __half2*)&x0;
        const __half2* p1 = (const __half2*)&x1;
        const __half2* p2 = (const __half2*)&x2;
        const __half2* p3 = (const __half2*)&x3;
#pragma unroll
        for (int p = 0; p < 4; p++) {
            float2 fa = __half22float2(p0[p]);
            float2 fb = __half22float2(p1[p]);
            float2 fc = __half22float2(p2[p]);
            float2 fd = __half22float2(p3[p]);
            acc[2 * p]     += a0 * fa.x + a1 * fb.x + a2 * fc.x + a3 * fd.x;
            acc[2 * p + 1] += a0 * fa.y + a1 * fb.y + a2 * fc.y + a3 * fd.y;
        }
    }
    for (; j < n; j += 4) {
        const float a0 = s_e[j] * inv;
        const uint4 xv = *((const uint4*)(Xh + (size_t)s_idx[j] * HID) + u);
        const __half2* p0 = (const __half2*)&xv;
#pragma unroll
        for (int p = 0; p < 4; p++) {
            float2 fa = __half22float2(p0[p]);
            acc[2 * p]     += a0 * fa.x;
            acc[2 * p + 1] += a0 * fa.y;
        }
    }
    ((float4*)(s_hq + q * HID))[u * 2] =
        make_float4(acc[0], acc[1], acc[2], acc[3]);
    ((float4*)(s_hq + q * HID))[u * 2 + 1] =
        make_float4(acc[4], acc[5], acc[6], acc[7]);
    __syncthreads();

    if (t < 128) {
        float4 r = make_float4(0.f, 0.f, 0.f, 0.f);
#pragma unroll
        for (int qq = 0; qq < 4; qq++) {
            float4 v = ((const float4*)s_hq)[qq * 128 + t];
            r.x += v.x; r.y += v.y; r.z += v.z; r.w += v.w;
        }
        r.x = (r.x > 0.f) ? r.x : (__expf(r.x) - 1.0f);
        r.y = (r.y > 0.f) ? r.y : (__expf(r.y) - 1.0f);
        r.z = (r.z > 0.f) ? r.z : (__expf(r.z) - 1.0f);
        r.w = (r.w > 0.f) ? r.w : (__expf(r.w) - 1.0f);
        ((float4*)s_h)[t] = r;
    }
    __syncthreads();

    if (t < 240) {
        int k  = t % 30;
        int sl = t / 30;
        float p = 0.0f;
        const int d0 = sl * 64;
#pragma unroll 8
        for (int d = d0; d < d0 + 64; d++) p += s_h[d] * W1[d * LAT + k];
        s_part[sl][k] = p;
    }
    __syncthreads();
    if (t < LAT) {
        float r = 0.0f;
#pragma unroll
        for (int sl = 0; sl < 8; sl++) r += s_part[sl][t];
        out[(size_t)row * LAT + t] = r;
    }
}

// -------------------- launch -------------------------------------------------
extern "C" void kernel_launch(void* const* d_in, const int* in_sizes, int n_in,
                              void* d_out, int out_size)
{
    const float* node_features = (const float*)d_in[0]; // [8192,3000]
    const float* graph         = (const float*)d_in[1]; // [8192,8192]
    const float* W0            = (const float*)d_in[2]; // [3000,512]
    const float* v0            = (const float*)d_in[3]; // [512]
    const float* v1            = (const float*)d_in[4]; // [512]
    const float* W1            = (const float*)d_in[5]; // [512,30]
    float* out = (float*)d_out;

    __half *Xh, *Bhi;
    float *f0, *f1;
    int *idx, *cnt;
    cudaGetSymbolAddress((void**)&Xh,  g_Xh);
    cudaGetSymbolAddress((void**)&f0,  g_f0);
    cudaGetSymbolAddress((void**)&f1,  g_f1);
    cudaGetSymbolAddress((void**)&idx, g_idx);
    cudaGetSymbolAddress((void**)&cnt, g_cnt);
    cudaGetSymbolAddress((void**)&Bhi, g_Bhi);

    static cudaStream_t s2 = nullptr;
    static cudaEvent_t evFork = nullptr, evB = nullptr;
    if (s2 == nullptr) {
        cudaStreamCreateWithFlags(&s2, cudaStreamNonBlocking);
        cudaEventCreateWithFlags(&evFork, cudaEventDisableTiming);
        cudaEventCreateWithFlags(&evB,    cudaEventDisableTiming);
        cudaFuncSetAttribute(gemm_mma_kernel,
                             cudaFuncAttributeMaxDynamicSharedMemorySize,
                             SMEM_TOTAL);
    }

    // s2: convB (tiny) overlaps sparsify
    cudaEventRecord(evFork, 0);
    cudaStreamWaitEvent(s2, evFork, 0);
    convB_kernel<<<dim3(K_PAD / 32, HID / 32), dim3(32, 8), 0, s2>>>(W0, Bhi);
    cudaEventRecord(evB, s2);

    // main: f0/f1 init + sparsify at full chip, then fused GEMM, then attn
    cudaMemsetAsync(f0, 0, M_N * sizeof(float), 0);
    cudaMemsetAsync(f1, 0, M_N * sizeof(float), 0);
    sparsify_kernel<<<M_N, 512>>>(graph, idx, cnt);
    cudaStreamWaitEvent(0, evB, 0);
    gemm_mma_kernel<<<dim3(HID / BN, M_N / BM), 512, SMEM_TOTAL>>>(
        node_features, Xh, v0, v1, f0, f1);
    attn_kernel<<<M_N, 256>>>(Xh, f0, f1, W1, idx, cnt, out);
}

// round 17
// speedup vs baseline: 1.5690x; 1.0369x over previous
#include <cuda_runtime.h>
#include <cuda_fp16.h>
#include <math.h>
#include <stdint.h>

// -------------------- problem constants --------------------
#define M_N     8192
#define IN_DIM  3000
#define K_PAD   3008        // 47 * 64
#define HID     512
#define LAT     30
#define LATP    32          // padded LAT for W1t
#define MAXD    192

#define BM      128
#define BN      256
#define BK      64
#define NCHUNK  (K_PAD / BK)   // 47

// SMEM stage layout (bytes): Ah[128x64] fp16 = 16K, Bh[256x64] fp16 = 32K
#define A_BYTES   16384
#define B_BYTES   32768
#define STAGE     (A_BYTES + B_BYTES)            // 49152
#define SMEM_TOTAL (2 * STAGE)                   // 98304 (2-stage, R6 config)

// -------------------- static device scratch --------------------
__device__ __align__(16) __half g_Xh[(size_t)M_N * HID];      // 8 MB fp16 X
__device__ __align__(16) __half g_Hh[(size_t)M_N * HID];      // 8 MB fp16 H
__device__ float g_f0[M_N];
__device__ float g_f1[M_N];
__device__ int   g_idx[M_N * MAXD];
__device__ int   g_cnt[M_N];
__device__ __align__(16) __half g_Bhi[(size_t)HID * K_PAD];   // [n][k] fp16
__device__ __align__(16) __half g_W1t[LATP * HID];            // [k][d] fp16

// -------------------- PTX helpers --------------------
__device__ __forceinline__ uint32_t smem_u32(const void* p) {
    uint32_t a;
    asm("{ .reg .u64 t; cvta.to.shared.u64 t, %1; cvt.u32.u64 %0, t; }"
        : "=r"(a) : "l"(p));
    return a;
}

__device__ __forceinline__ uint32_t sw128(uint32_t off) {
    return off ^ ((off >> 3) & 0x70);
}

__device__ __forceinline__ void cp_async16(uint32_t dst, const void* src) {
    asm volatile("cp.async.cg.shared.global [%0], [%1], 16;"
                 :: "r"(dst), "l"(src));
}
__device__ __forceinline__ void cp_commit() {
    asm volatile("cp.async.commit_group;" ::: "memory");
}

__device__ __forceinline__ void ldmx4(uint32_t* r, uint32_t addr) {
    asm volatile("ldmatrix.sync.aligned.m8n8.x4.shared.b16 {%0,%1,%2,%3}, [%4];"
                 : "=r"(r[0]), "=r"(r[1]), "=r"(r[2]), "=r"(r[3]) : "r"(addr));
}

__device__ __forceinline__ void mma_fp16(float* d, const uint32_t* a,
                                         const uint32_t* b) {
    asm volatile(
        "mma.sync.aligned.m16n8k16.row.col.f32.f16.f16.f32 "
        "{%0,%1,%2,%3}, {%4,%5,%6,%7}, {%8,%9}, {%0,%1,%2,%3};"
        : "+f"(d[0]), "+f"(d[1]), "+f"(d[2]), "+f"(d[3])
        : "r"(a[0]), "r"(a[1]), "r"(a[2]), "r"(a[3]), "r"(b[0]), "r"(b[1]));
}

// -------------------- Kernel 0a: transpose W0 -> [n][k] fp16 ----------------
__global__ void convB_kernel(const float* __restrict__ W,
                             __half* __restrict__ hi)
{
    __shared__ float tile[32][33];
    int k0 = blockIdx.x * 32;
    int n0 = blockIdx.y * 32;
    int tx = threadIdx.x, ty = threadIdx.y;   // block (32, 8)
#pragma unroll
    for (int r = 0; r < 4; r++) {
        int kk = ty + r * 8;
        int k  = k0 + kk;
        tile[kk][tx] = (k < IN_DIM) ? W[(size_t)k * HID + n0 + tx] : 0.0f;
    }
    __syncthreads();
#pragma unroll
    for (int r = 0; r < 4; r++) {
        int nn = ty + r * 8;
        hi[(size_t)(n0 + nn) * K_PAD + k0 + tx] = __float2half(tile[tx][nn]);
    }
}

// -------------------- Kernel 0b: W1 -> W1t[k][d] fp16 -----------------------
__global__ void convW1_kernel(const float* __restrict__ W1,
                              __half* __restrict__ W1t)
{
    for (int i = threadIdx.x; i < LATP * HID; i += 256) {
        int k = i / HID;
        int d = i % HID;
        W1t[i] = (k < LAT) ? __float2half(W1[d * LAT + k]) : __half(0.0f);
    }
}

// -------------------- Kernel 1: fused-A fp16 warp-MMA GEMM ------------------
__device__ __forceinline__ void ldgA(const float* __restrict__ Abase, int k0,
                                     int t, bool last, float4* v)
{
#pragma unroll
    for (int i = 0; i < 4; i++) {
        int lin = t + i * 512;
        int row = lin >> 4, seg = lin & 15;
        if (last && seg >= 14) {            // cols >= 3000 -> zero pad
            v[i] = make_float4(0.f, 0.f, 0.f, 0.f);
        } else {
            v[i] = *(const float4*)(Abase + (size_t)row * IN_DIM + k0 + seg * 4);
        }
    }
}

__device__ __forceinline__ void stsA(uint32_t base, int t, const float4* v)
{
#pragma unroll
    for (int i = 0; i < 4; i++) {
        int lin = t + i * 512;
        int row = lin >> 4, seg = lin & 15;
        float4 a = v[i];
        __half2 hA = __floats2half2_rn(a.x, a.y);
        __half2 hB = __floats2half2_rn(a.z, a.w);
        uint32_t off = sw128((uint32_t)(row * 128 + seg * 8));
        asm volatile("st.shared.v2.u32 [%0], {%1, %2};"
                     :: "r"(base + off),
                        "r"(*(const uint32_t*)&hA), "r"(*(const uint32_t*)&hB)
                     : "memory");
    }
}

__device__ __forceinline__ void ldgB(uint32_t base, int k0, int t,
                                     const __half* Bh)
{
#pragma unroll
    for (int i = 0; i < 4; i++) {
        int lin = t + i * 512;
        int row = lin >> 3, seg = lin & 7;
        uint32_t so = sw128((uint32_t)(row * 128 + seg * 16));
        cp_async16(base + A_BYTES + so,
                   Bh + (size_t)row * K_PAD + k0 + seg * 8);
    }
}

__global__ __launch_bounds__(512, 1)
void gemm_mma_kernel(const float* __restrict__ A, __half* __restrict__ Xout,
                     const float* __restrict__ v0,
                     const float* __restrict__ v1,
                     float* __restrict__ f0, float* __restrict__ f1)
{
    extern __shared__ __align__(1024) char smem[];
    const uint32_t sb = smem_u32(smem);
    const int t    = threadIdx.x;
    const int wid  = t >> 5;
    const int lane = t & 31;
    const int wy   = wid >> 2;   // 0..3 : m group (32 rows)
    const int wx   = wid & 3;    // 0..3 : n group (64 cols)

    const float* Abase = A + (size_t)(blockIdx.y * BM) * IN_DIM;
    const __half* Bh = g_Bhi + (size_t)(blockIdx.x * BN) * K_PAD;

    float acc[2][8][4];
#pragma unroll
    for (int i = 0; i < 2; i++)
#pragma unroll
        for (int j = 0; j < 8; j++)
#pragma unroll
            for (int q = 0; q < 4; q++) acc[i][j][q] = 0.0f;

    const int a_row = (lane & 15);
    const int a_k8  = (lane >> 4);
    const int b_row = ((lane >> 4) << 3) + (lane & 7);
    const int b_k8  = (lane >> 3) & 1;

    // prologue: chunk 0
    {
        float4 v[4];
        ldgA(Abase, 0, t, false, v);
        stsA(sb, t, v);
        ldgB(sb, 0, t, Bh);
        cp_commit();
    }

    float4 vnext[4];
    for (int c = 0; c < NCHUNK; c++) {
        asm volatile("cp.async.wait_group 0;" ::: "memory");
        __syncthreads();

        const bool pref = (c + 1 < NCHUNK);
        if (pref) {
            ldgA(Abase, (c + 1) * BK, t, (c + 1) == NCHUNK - 1, vnext);
            ldgB(sb + ((c + 1) & 1) * STAGE, (c + 1) * BK, t, Bh);
            cp_commit();
        }

        const uint32_t base = sb + (c & 1) * STAGE;
        const uint32_t aH = base;
        const uint32_t bH = base + A_BYTES;

#pragma unroll
        for (int kk = 0; kk < 4; kk++) {
            uint32_t ah[2][4];
#pragma unroll
            for (int mt = 0; mt < 2; mt++) {
                int row = wy * 32 + mt * 16 + a_row;
                int kcol = kk * 16 + a_k8 * 8;
                uint32_t off = sw128((uint32_t)(row * 128 + kcol * 2));
                ldmx4(ah[mt], aH + off);
            }
#pragma unroll
            for (int ng = 0; ng < 4; ng++) {
                int n = wx * 64 + ng * 16 + b_row;
                int kcol = kk * 16 + b_k8 * 8;
                uint32_t off = sw128((uint32_t)(n * 128 + kcol * 2));
                uint32_t bh[4];
                ldmx4(bh, bH + off);
#pragma unroll
                for (int mt = 0; mt < 2; mt++) {
                    mma_fp16(acc[mt][2 * ng],     ah[mt], bh);
                    mma_fp16(acc[mt][2 * ng + 1], ah[mt], bh + 2);
                }
            }
        }

        if (pref) stsA(sb + ((c + 1) & 1) * STAGE, t, vnext);
        // top-of-loop __syncthreads orders these STS before next compute
    }

    // epilogue: write fp16 X and fused f0/f1 partial dot products
    const int colbase = blockIdx.x * BN + wx * 64;
    __half* dst = Xout + (size_t)(blockIdx.y * BM + wy * 32) * HID + colbase;
    const int r0 = lane >> 2;
    const int c0 = (lane & 3) * 2;

#pragma unroll
    for (int mt = 0; mt < 2; mt++) {
        float d0 = 0.0f, d1 = 0.0f;
        float e0 = 0.0f, e1 = 0.0f;
#pragma unroll
        for (int nt = 0; nt < 8; nt++) {
            __half2 h01 = __floats2half2_rn(acc[mt][nt][0], acc[mt][nt][1]);
            __half2 h23 = __floats2half2_rn(acc[mt][nt][2], acc[mt][nt][3]);
            *(__half2*)(dst + (size_t)(mt * 16 + r0) * HID + nt * 8 + c0) = h01;
            *(__half2*)(dst + (size_t)(mt * 16 + r0 + 8) * HID + nt * 8 + c0) = h23;
            float2 w0v = *(const float2*)(v0 + colbase + nt * 8 + c0);
            float2 w1v = *(const float2*)(v1 + colbase + nt * 8 + c0);
            float2 x01 = __half22float2(h01);
            float2 x23 = __half22float2(h23);
            d0 += x01.x * w0v.x + x01.y * w0v.y;
            d1 += x01.x * w1v.x + x01.y * w1v.y;
            e0 += x23.x * w0v.x + x23.y * w0v.y;
            e1 += x23.x * w1v.x + x23.y * w1v.y;
        }
#pragma unroll
        for (int o = 2; o > 0; o >>= 1) {
            d0 += __shfl_xor_sync(0xffffffffu, d0, o);
            d1 += __shfl_xor_sync(0xffffffffu, d1, o);
            e0 += __shfl_xor_sync(0xffffffffu, e0, o);
            e1 += __shfl_xor_sync(0xffffffffu, e1, o);
        }
        if ((lane & 3) == 0) {
            int rowA = blockIdx.y * BM + wy * 32 + mt * 16 + r0;
            atomicAdd(&f0[rowA], d0);
            atomicAdd(&f1[rowA], d1);
            atomicAdd(&f0[rowA + 8], e0);
            atomicAdd(&f1[rowA + 8], e1);
        }
    }
}

// -------------------- Kernel 3: sparsify graph rows -------------------------
__global__ __launch_bounds__(512)
void sparsify_kernel(const float* __restrict__ graph,
                     int* __restrict__ idx, int* __restrict__ cnt)
{
    int row = blockIdx.x;
    __shared__ int c;
    if (threadIdx.x == 0) c = 0;
    __syncthreads();
    const float4* g = (const float4*)(graph + (size_t)row * M_N);
    const int t = threadIdx.x;
    float4 v[4];
#pragma unroll
    for (int i = 0; i < 4; i++) v[i] = __ldg(&g[t + i * 512]);
#pragma unroll
    for (int i = 0; i < 4; i++) {
        int b = (t + i * 512) * 4;
        if (v[i].x != 0.0f) { int s = atomicAdd(&c, 1); if (s < MAXD) idx[row * MAXD + s] = b + 0; }
        if (v[i].y != 0.0f) { int s = atomicAdd(&c, 1); if (s < MAXD) idx[row * MAXD + s] = b + 1; }
        if (v[i].z != 0.0f) { int s = atomicAdd(&c, 1); if (s < MAXD) idx[row * MAXD + s] = b + 2; }
        if (v[i].w != 0.0f) { int s = atomicAdd(&c, 1); if (s < MAXD) idx[row * MAXD + s] = b + 3; }
    }
    __syncthreads();
    if (threadIdx.x == 0) cnt[row] = (c < MAXD) ? c : MAXD;
}

// -------------------- Kernel 4: attention + aggregation + ELU -> Hh ---------
// Block-per-row; ends at ELU, writes fp16 H. W1 phase removed (it was ~80%
// of this kernel's L1 wavefronts per R16 ncu).
__global__ __launch_bounds__(256)
void attn_kernel(const __half* __restrict__ Xh,
                 const float* __restrict__ f0, const float* __restrict__ f1,
                 const int* __restrict__ idx, const int* __restrict__ cnt,
                 __half* __restrict__ Hh)
{
    const int row = blockIdx.x;
    const int t   = threadIdx.x;

    __shared__ __align__(16) float s_hq[4 * HID];
    __shared__ __align__(16) float s_e[MAXD];
    __shared__ int   s_idx[MAXD];
    __shared__ float s_inv;

    const int n = cnt[row];              // 1..MAXD (self loop guarantees >=1)

    if (t < n) {
        int id = idx[row * MAXD + t];
        s_idx[t] = id;
        float e   = f0[row] + f1[id];
        float sig = 1.0f / (1.0f + __expf(-e));
        s_e[t] = __expf(sig - 0.5f);
    }
    __syncthreads();

    if (t < 32) {
        float s = 0.0f;
        for (int j = t; j < n; j += 32) s += s_e[j];
#pragma unroll
        for (int o = 16; o > 0; o >>= 1) s += __shfl_xor_sync(0xffffffffu, s, o);
        if (t == 0) s_inv = 1.0f / fmaxf(s, 1e-30f);
    }
    __syncthreads();
    const float inv = s_inv;

    // aggregation: quarter q handles neighbors j ≡ q (mod 4), unrolled x4
    const int q = t >> 6;
    const int u = t & 63;
    float acc[8];
#pragma unroll
    for (int i = 0; i < 8; i++) acc[i] = 0.0f;

    int j = q;
    for (; j + 12 < n; j += 16) {
        float a0 = s_e[j] * inv,      a1 = s_e[j + 4] * inv;
        float a2 = s_e[j + 8] * inv,  a3 = s_e[j + 12] * inv;
        uint4 x0 = *((const uint4*)(Xh + (size_t)s_idx[j]      * HID) + u);
        uint4 x1 = *((const uint4*)(Xh + (size_t)s_idx[j + 4]  * HID) + u);
        uint4 x2 = *((const uint4*)(Xh + (size_t)s_idx[j + 8]  * HID) + u);
        uint4 x3 = *((const uint4*)(Xh + (size_t)s_idx[j + 12] * HID) + u);
        const __half2* p0 = (const __half2*)&x0;
        const __half2* p1 = (const __half2*)&x1;
        const __half2* p2 = (const __half2*)&x2;
        const __half2* p3 = (const __half2*)&x3;
#pragma unroll
        for (int p = 0; p < 4; p++) {
            float2 fa = __half22float2(p0[p]);
            float2 fb = __half22float2(p1[p]);
            float2 fc = __half22float2(p2[p]);
            float2 fd = __half22float2(p3[p]);
            acc[2 * p]     += a0 * fa.x + a1 * fb.x + a2 * fc.x + a3 * fd.x;
            acc[2 * p + 1] += a0 * fa.y + a1 * fb.y + a2 * fc.y + a3 * fd.y;
        }
    }
    for (; j < n; j += 4) {
        const float a0 = s_e[j] * inv;
        const uint4 xv = *((const uint4*)(Xh + (size_t)s_idx[j] * HID) + u);
        const __half2* p0 = (const __half2*)&xv;
#pragma unroll
        for (int p = 0; p < 4; p++) {
            float2 fa = __half22float2(p0[p]);
            acc[2 * p]     += a0 * fa.x;
            acc[2 * p + 1] += a0 * fa.y;
        }
    }
    ((float4*)(s_hq + q * HID))[u * 2] =
        make_float4(acc[0], acc[1], acc[2], acc[3]);
    ((float4*)(s_hq + q * HID))[u * 2 + 1] =
        make_float4(acc[4], acc[5], acc[6], acc[7]);
    __syncthreads();

    // reduce quarters + ELU, write fp16 H (thread t owns d = [4t, 4t+4))
    if (t < 128) {
        float4 r = make_float4(0.f, 0.f, 0.f, 0.f);
#pragma unroll
        for (int qq = 0; qq < 4; qq++) {
            float4 v = ((const float4*)s_hq)[qq * 128 + t];
            r.x += v.x; r.y += v.y; r.z += v.z; r.w += v.w;
        }
        r.x = (r.x > 0.f) ? r.x : (__expf(r.x) - 1.0f);
        r.y = (r.y > 0.f) ? r.y : (__expf(r.y) - 1.0f);
        r.z = (r.z > 0.f) ? r.z : (__expf(r.z) - 1.0f);
        r.w = (r.w > 0.f) ? r.w : (__expf(r.w) - 1.0f);
        __half2 h01 = __floats2half2_rn(r.x, r.y);
        __half2 h23 = __floats2half2_rn(r.z, r.w);
        *(uint2*)(Hh + (size_t)row * HID + 4 * t) =
            make_uint2(*(const uint32_t*)&h01, *(const uint32_t*)&h23);
    }
}

// -------------------- Kernel 5: out = H @ W1 (warp per row) -----------------
// W1t[32][512] fp16 staged coalesced into smem; lane owns uint4 #lane and
// #(lane+32) of the H row -> per-k LDS.128 x2 conflict-free.
__global__ __launch_bounds__(256)
void proj_kernel(const __half* __restrict__ Hh, const __half* __restrict__ W1t,
                 float* __restrict__ out)
{
    __shared__ __align__(16) __half sW[LATP * HID];   // 32 KB
    const int t = threadIdx.x;
    for (int i = t; i < LATP * HID / 8; i += 256)
        ((uint4*)sW)[i] = ((const uint4*)W1t)[i];
    __syncthreads();

    const int w    = t >> 5;
    const int lane = t & 31;
    const int row  = blockIdx.x * 8 + w;

    // load H row: lane owns halves [16*lane_grp...] via uint4 #lane, #(lane+32)
    const uint4* hrow = (const uint4*)(Hh + (size_t)row * HID);
    uint4 hv0 = hrow[lane];
    uint4 hv1 = hrow[lane + 32];
    float hf[16];
    {
        const __half2* p0 = (const __half2*)&hv0;
        const __half2* p1 = (const __half2*)&hv1;
#pragma unroll
        for (int p = 0; p < 4; p++) {
            float2 a = __half22float2(p0[p]);
            float2 b = __half22float2(p1[p]);
            hf[2 * p]         = a.x;
            hf[2 * p + 1]     = a.y;
            hf[8 + 2 * p]     = b.x;
            hf[8 + 2 * p + 1] = b.y;
        }
    }

    float acc[LAT];
#pragma unroll
    for (int k = 0; k < LAT; k++) {
        const uint4 w0 = *(const uint4*)(sW + k * HID + lane * 8);
        const uint4 w1 = *(const uint4*)(sW + k * HID + 256 + lane * 8);
        const __half2* q0 = (const __half2*)&w0;
        const __half2* q1 = (const __half2*)&w1;
        float s = 0.0f;
#pragma unroll
        for (int p = 0; p < 4; p++) {
            float2 a = __half22float2(q0[p]);
            float2 b = __half22float2(q1[p]);
            s += hf[2 * p] * a.x + hf[2 * p + 1] * a.y;
            s += hf[8 + 2 * p] * b.x + hf[8 + 2 * p + 1] * b.y;
        }
        acc[k] = s;
    }
#pragma unroll
    for (int o = 16; o > 0; o >>= 1)
#pragma unroll
        for (int k = 0; k < LAT; k++)
            acc[k] += __shfl_xor_sync(0xffffffffu, acc[k], o);

    if (lane == 0) {
        float* op = out + (size_t)row * LAT;
#pragma unroll
        for (int k = 0; k < LAT; k++) op[k] = acc[k];
    }
}

// -------------------- launch -------------------------------------------------
extern "C" void kernel_launch(void* const* d_in, const int* in_sizes, int n_in,
                              void* d_out, int out_size)
{
    const float* node_features = (const float*)d_in[0]; // [8192,3000]
    const float* graph         = (const float*)d_in[1]; // [8192,8192]
    const float* W0            = (const float*)d_in[2]; // [3000,512]
    const float* v0            = (const float*)d_in[3]; // [512]
    const float* v1            = (const float*)d_in[4]; // [512]
    const float* W1            = (const float*)d_in[5]; // [512,30]
    float* out = (float*)d_out;

    __half *Xh, *Hh, *Bhi, *W1t;
    float *f0, *f1;
    int *idx, *cnt;
    cudaGetSymbolAddress((void**)&Xh,  g_Xh);
    cudaGetSymbolAddress((void**)&Hh,  g_Hh);
    cudaGetSymbolAddress((void**)&f0,  g_f0);
    cudaGetSymbolAddress((void**)&f1,  g_f1);
    cudaGetSymbolAddress((void**)&idx, g_idx);
    cudaGetSymbolAddress((void**)&cnt, g_cnt);
    cudaGetSymbolAddress((void**)&Bhi, g_Bhi);
    cudaGetSymbolAddress((void**)&W1t, g_W1t);

    static cudaStream_t s2 = nullptr;
    static cudaEvent_t evFork = nullptr, evB = nullptr;
    if (s2 == nullptr) {
        cudaStreamCreateWithFlags(&s2, cudaStreamNonBlocking);
        cudaEventCreateWithFlags(&evFork, cudaEventDisableTiming);
        cudaEventCreateWithFlags(&evB,    cudaEventDisableTiming);
        cudaFuncSetAttribute(gemm_mma_kernel,
                             cudaFuncAttributeMaxDynamicSharedMemorySize,
                             SMEM_TOTAL);
    }

    // s2: convB + convW1 (tiny) overlap sparsify
    cudaEventRecord(evFork, 0);
    cudaStreamWaitEvent(s2, evFork, 0);
    convB_kernel<<<dim3(K_PAD / 32, HID / 32), dim3(32, 8), 0, s2>>>(W0, Bhi);
    convW1_kernel<<<1, 256, 0, s2>>>(W1, W1t);
    cudaEventRecord(evB, s2);

    // main: f0/f1 init + sparsify at full chip, then fused GEMM, attn, proj
    cudaMemsetAsync(f0, 0, M_N * sizeof(float), 0);
    cudaMemsetAsync(f1, 0, M_N * sizeof(float), 0);
    sparsify_kernel<<<M_N, 512>>>(graph, idx, cnt);
    cudaStreamWaitEvent(0, evB, 0);
    gemm_mma_kernel<<<dim3(HID / BN, M_N / BM), 512, SMEM_TOTAL>>>(
        node_features, Xh, v0, v1, f0, f1);
    attn_kernel<<<M_N, 256>>>(Xh, f0, f1, idx, cnt, Hh);
    proj_kernel<<<M_N / 8, 256>>>(Hh, W1t, out);
}